// round 14
// baseline (speedup 1.0000x reference)
#include <cuda_runtime.h>
#include <cuda_bf16.h>
#include <cstdint>

#define NCLS 10
#define DIM  128
#define BATCH 4                         // rows per warp per iteration
#define ACC_WARPS 4
#define ACC_THREADS 128
#define ACC_GRID 740                    // 5 blocks/SM * 148 SMs  (R12 had 8/SM)
#define ACC_TOTAL_WARPS (ACC_GRID * ACC_WARPS)   // 2960

#define CNT_GRID 296
#define CNT_THREADS 256

#define WSLOT 1600                      // floats per warp copy: 1280 sum + 320 q
#define NFINAL (NCLS * DIM + NCLS)      // 1280 sums + 10 class sum-of-squares

// Allocation-free scratch. g_final zeroed by the zero+count kernel each launch
// (deterministic replay); g_pcnt is overwritten (no zeroing needed).
__device__ float        g_final[NFINAL];
__device__ unsigned int g_pcnt[CNT_GRID * NCLS];

// ---------------------------------------------------------------------------
// Kernel 1: zero g_final + per-block label histogram (counts stay out of the
// hot accum loop). Per-warp smem counters -> per-block partial counts.
// ---------------------------------------------------------------------------
__global__ __launch_bounds__(CNT_THREADS)
void CLIR_zero_count_kernel(const int* __restrict__ t, int N) {
    __shared__ unsigned int hc[CNT_THREADS / 32][NCLS];
    const int tid  = threadIdx.x;
    const int warp = tid >> 5;

    for (int i = blockIdx.x * CNT_THREADS + tid; i < NFINAL;
         i += CNT_GRID * CNT_THREADS)
        g_final[i] = 0.0f;

    if (tid < NCLS * (CNT_THREADS / 32)) hc[tid / NCLS][tid % NCLS] = 0u;
    __syncthreads();

    const int N4 = N >> 2;
    const int4* t4 = (const int4*)t;
    for (int i = blockIdx.x * CNT_THREADS + tid; i < N4;
         i += CNT_GRID * CNT_THREADS) {
        const int4 l = __ldg(&t4[i]);
        atomicAdd(&hc[warp][l.x], 1u);
        atomicAdd(&hc[warp][l.y], 1u);
        atomicAdd(&hc[warp][l.z], 1u);
        atomicAdd(&hc[warp][l.w], 1u);
    }
    if (blockIdx.x == 0 && tid < (N & 3))
        atomicAdd(&hc[0][__ldg(t + (N4 << 2) + tid)], 1u);
    __syncthreads();

    if (tid < NCLS) {
        unsigned s = 0;
        #pragma unroll
        for (int w = 0; w < CNT_THREADS / 32; w++) s += hc[w][tid];
        g_pcnt[blockIdx.x * NCLS + tid] = s;    // overwrite: deterministic
    }
}

// ---------------------------------------------------------------------------
// Kernel 2: streaming accumulation (R2 structure + sumsq-scalar trick).
// Per-warp PRIVATE smem copy: per-class sums (lane l owns features 4l..4l+3)
// + per-(class,lane) scalar sumsq partial. Branch-free: class indexes smem.
// Crossbar: 1280 B/row = 10 cyc/row. 5 blocks/SM => 128 KB smem, ~100 KB L1
// left for LDG staging (R12's 8 blocks/SM left 23 KB and collapsed).
// ---------------------------------------------------------------------------
#define ROW(v, c) do {                                                \
    float4* ps = (float4*)(ws + (c) * DIM + lane * 4);                \
    float4 a = *ps;                                                   \
    a.x += (v).x; a.y += (v).y; a.z += (v).z; a.w += (v).w;           \
    *ps = a;                                                          \
    float d = fmaf((v).y,(v).y,(v).x*(v).x)                           \
            + fmaf((v).w,(v).w,(v).z*(v).z);                          \
    wq[(c) * 32 + lane] += d;                                         \
} while (0)

__global__ __launch_bounds__(ACC_THREADS, 5)
void CLIR_accum_kernel(const float* __restrict__ x,
                       const int*   __restrict__ t,
                       int N) {
    __shared__ float acc[ACC_WARPS][WSLOT];   // 25.6 KB/block

    const int tid  = threadIdx.x;
    const int lane = tid & 31;
    const int warp = tid >> 5;
    const int gw   = blockIdx.x * ACC_WARPS + warp;

    for (int i = tid; i < ACC_WARPS * WSLOT; i += ACC_THREADS)
        (&acc[0][0])[i] = 0.0f;
    __syncthreads();

    float* ws = acc[warp];                    // sums: [c*128 + feat]
    float* wq = acc[warp] + NCLS * DIM;       // q:    [c*32 + lane]
    const float4* __restrict__ x4 = (const float4*)x;

    for (int base = gw * BATCH; base < N; base += ACC_TOTAL_WARPS * BATCH) {
        if (base + BATCH <= N) {
            const int4 lab = __ldg((const int4*)(t + base));
            const size_t r = (size_t)base * (DIM / 4) + lane;
            const float4 v0 = x4[r + 0 * 32];
            const float4 v1 = x4[r + 1 * 32];
            const float4 v2 = x4[r + 2 * 32];
            const float4 v3 = x4[r + 3 * 32];
            ROW(v0, lab.x);
            ROW(v1, lab.y);
            ROW(v2, lab.z);
            ROW(v3, lab.w);
        } else {
            for (int j = 0; base + j < N; j++) {
                const int c = __ldg(t + base + j);
                const float4 v = x4[(size_t)(base + j) * (DIM / 4) + lane];
                ROW(v, c);
            }
        }
    }
    __syncthreads();

    // Fold 4 warp copies -> spread global float atomics (REDG).
    for (int i = tid; i < NCLS * DIM; i += ACC_THREADS) {
        const float v = acc[0][i] + acc[1][i] + acc[2][i] + acc[3][i];
        atomicAdd(&g_final[i], v);
    }
    for (int i = tid; i < NCLS * 32; i += ACC_THREADS) {
        const float v = acc[0][NCLS * DIM + i] + acc[1][NCLS * DIM + i]
                      + acc[2][NCLS * DIM + i] + acc[3][NCLS * DIM + i];
        atomicAdd(&g_final[NCLS * DIM + (i >> 5)], v);
    }
}
#undef ROW

// ---------------------------------------------------------------------------
// penalty = (1/C) * Σ_c [ q_c/(n_c-1) - Σ_d sum[c][d]^2 / (n_c (n_c-1)) ]
// ---------------------------------------------------------------------------
__global__ void CLIR_finalize_kernel(float* __restrict__ out) {
    __shared__ unsigned int ic[NCLS];
    __shared__ float scnt[NCLS];
    const int d = threadIdx.x;   // 128 threads
    if (d < NCLS) ic[d] = 0u;
    __syncthreads();
    for (int j = d; j < CNT_GRID * NCLS; j += 128)
        atomicAdd(&ic[j % NCLS], g_pcnt[j]);
    __syncthreads();
    if (d < NCLS) scnt[d] = (float)ic[d];
    __syncthreads();

    float p = 0.0f;
    #pragma unroll
    for (int c = 0; c < NCLS; c++) {
        const float n = scnt[c];
        const float s = g_final[c * DIM + d];
        p += (s * s) / (n * (n - 1.0f));
    }
    #pragma unroll
    for (int o = 16; o > 0; o >>= 1)
        p += __shfl_xor_sync(0xFFFFFFFFu, p, o);
    __shared__ float wr[4];
    if ((d & 31) == 0) wr[d >> 5] = p;
    __syncthreads();
    if (d == 0) {
        float tr = 0.0f;
        #pragma unroll
        for (int c = 0; c < NCLS; c++)
            tr += g_final[NCLS * DIM + c] / (scnt[c] - 1.0f);
        out[0] = (tr - (wr[0] + wr[1] + wr[2] + wr[3])) * (1.0f / (float)NCLS);
    }
}

extern "C" void kernel_launch(void* const* d_in, const int* in_sizes, int n_in,
                              void* d_out, int out_size) {
    const float* x = (const float*)d_in[0];
    const int*   t = (const int*)d_in[1];
    const int N = in_sizes[1];

    CLIR_zero_count_kernel<<<CNT_GRID, CNT_THREADS>>>(t, N);
    CLIR_accum_kernel<<<ACC_GRID, ACC_THREADS>>>(x, t, N);
    CLIR_finalize_kernel<<<1, DIM>>>((float*)d_out);
}

// round 15
// speedup vs baseline: 1.0052x; 1.0052x over previous
#include <cuda_runtime.h>
#include <cuda_bf16.h>

#define NCLS 10
#define DIM  128
#define WARPS_PER_BLOCK 4
#define BLOCK_THREADS   (WARPS_PER_BLOCK * 32)
#define GRID_BLOCKS     740   // 148 SMs * 5 blocks (smem-padded to force 5/SM)

#define NFINAL (NCLS * DIM + NCLS)   // 1280 sums + 10 class sum-of-squares

// Global scratch (allocation-free), zeroed every launch -> deterministic replay.
__device__ float        g_final[NFINAL];
__device__ unsigned int g_cnt[NCLS];

__global__ void CLIR_zero_kernel() {
    int i = blockIdx.x * blockDim.x + threadIdx.x;
    if (i < NFINAL) g_final[i] = 0.0f;
    if (i < NCLS)   g_cnt[i] = 0u;
}

// ---------------------------------------------------------------------------
// EXACT R2 structure (113.4us measured) with ONE change: the sum-of-squares
// accumulator is a per-(class,lane) SCALAR instead of a float4, cutting the
// per-row smem RMW from 2048B to 1280B. s_sq keeps its full R2-size
// declaration so static smem (~41KB) pins residency at R2's 5 blocks/SM.
// One warp = one row per iteration: 32 lanes x float4 = the full 512B row.
// Per-warp private copies -> no atomics, no races in the hot loop.
// ---------------------------------------------------------------------------
__global__ __launch_bounds__(BLOCK_THREADS)
void CLIR_accum_kernel(const float* __restrict__ x,
                       const int*   __restrict__ t,
                       int N) {
    __shared__ float s_sum[WARPS_PER_BLOCK][NCLS * DIM];   // 20 KB (used)
    __shared__ float s_sq [WARPS_PER_BLOCK][NCLS * DIM];   // 20 KB (320/1280 used; pad)
    __shared__ unsigned int s_cnt[NCLS];

    const int tid  = threadIdx.x;
    const int lane = tid & 31;
    const int w    = tid >> 5;

    // Zero shared accumulators (same as R2).
    float* s_sum_flat = &s_sum[0][0];
    float* s_sq_flat  = &s_sq[0][0];
    for (int i = tid; i < WARPS_PER_BLOCK * NCLS * DIM; i += BLOCK_THREADS) {
        s_sum_flat[i] = 0.0f;
        s_sq_flat[i]  = 0.0f;
    }
    if (tid < NCLS) s_cnt[tid] = 0u;
    __syncthreads();

    float* ms = s_sum[w];                 // per-class sums: [c*128 + feat]
    float* mq = s_sq[w];                  // per-class q:    [c*32 + lane]
    const float4* __restrict__ x4 = (const float4*)x;

    for (int row = blockIdx.x * WARPS_PER_BLOCK + w; row < N;
         row += GRID_BLOCKS * WARPS_PER_BLOCK) {
        const int c = __ldg(&t[row]);                        // warp-uniform
        const float4 v = x4[(size_t)row * (DIM / 4) + lane]; // 512B/warp coalesced

        float4* ps = (float4*)(ms + c * DIM + lane * 4);
        float4 a = *ps;
        a.x += v.x; a.y += v.y; a.z += v.z; a.w += v.w;
        *ps = a;

        const float d = fmaf(v.y, v.y, v.x * v.x)
                      + fmaf(v.w, v.w, v.z * v.z);
        mq[c * 32 + lane] += d;                              // scalar RMW (the change)

        if (lane == 0) atomicAdd(&s_cnt[c], 1u);
    }
    __syncthreads();

    // Fold the 4 warp-copies and push to global via spread float atomics.
    for (int i = tid; i < NCLS * DIM; i += BLOCK_THREADS) {
        const float vs = s_sum[0][i] + s_sum[1][i] + s_sum[2][i] + s_sum[3][i];
        atomicAdd(&g_final[i], vs);
    }
    for (int i = tid; i < NCLS * 32; i += BLOCK_THREADS) {
        const float vq = s_sq[0][i] + s_sq[1][i] + s_sq[2][i] + s_sq[3][i];
        atomicAdd(&g_final[NCLS * DIM + (i >> 5)], vq);
    }
    if (tid < NCLS) atomicAdd(&g_cnt[tid], s_cnt[tid]);
}

// ---------------------------------------------------------------------------
// penalty = (1/C) * Sum_c [ q_c/(n_c-1) - Sum_d sum[c][d]^2 / (n_c (n_c-1)) ]
// (same finalize math as R14, which verified at rel_err 1.6e-5)
// ---------------------------------------------------------------------------
__global__ void CLIR_finalize_kernel(float* __restrict__ out) {
    __shared__ float scnt[NCLS];
    const int d = threadIdx.x;   // 128 threads
    if (d < NCLS) scnt[d] = (float)g_cnt[d];
    __syncthreads();

    float p = 0.0f;
    #pragma unroll
    for (int c = 0; c < NCLS; c++) {
        const float n = scnt[c];
        const float s = g_final[c * DIM + d];
        p += (s * s) / (n * (n - 1.0f));
    }
    #pragma unroll
    for (int o = 16; o > 0; o >>= 1)
        p += __shfl_xor_sync(0xFFFFFFFFu, p, o);
    __shared__ float wr[4];
    if ((d & 31) == 0) wr[d >> 5] = p;
    __syncthreads();
    if (d == 0) {
        float tr = 0.0f;
        #pragma unroll
        for (int c = 0; c < NCLS; c++)
            tr += g_final[NCLS * DIM + c] / (scnt[c] - 1.0f);
        out[0] = (tr - (wr[0] + wr[1] + wr[2] + wr[3])) * (1.0f / (float)NCLS);
    }
}

extern "C" void kernel_launch(void* const* d_in, const int* in_sizes, int n_in,
                              void* d_out, int out_size) {
    const float* x = (const float*)d_in[0];
    const int*   t = (const int*)d_in[1];
    const int N = in_sizes[1];

    CLIR_zero_kernel<<<(NFINAL + 255) / 256, 256>>>();
    CLIR_accum_kernel<<<GRID_BLOCKS, BLOCK_THREADS>>>(x, t, N);
    CLIR_finalize_kernel<<<1, DIM>>>((float*)d_out);
}

// round 16
// speedup vs baseline: 3.0776x; 3.0616x over previous
#include <cuda_runtime.h>
#include <cuda_bf16.h>

#define NCLS 10
#define DIM  128
#define WARPS_PER_BLOCK 4
#define BLOCK_THREADS   (WARPS_PER_BLOCK * 32)
#define GRID_BLOCKS     740   // 148 SMs * 5 blocks (smem-limited occupancy)

// Global scratch (allocation-free), zeroed every launch -> deterministic replay.
__device__ float        g_sum[NCLS * DIM];
__device__ float        g_sq [NCLS * DIM];
__device__ unsigned int g_cnt[NCLS];

__global__ void CLIR_zero_kernel() {
    int i = blockIdx.x * blockDim.x + threadIdx.x;
    if (i < NCLS * DIM) { g_sum[i] = 0.0f; g_sq[i] = 0.0f; }
    if (i < NCLS) g_cnt[i] = 0u;
}

// ---------------------------------------------------------------------------
// EXACT R2 (113.4us measured) with ONE change: TWO rows per warp per
// iteration (2 independent LDG.128/lane + one int2 label load), doubling
// in-flight bytes per warp (512B -> 1024B) to test the latency-bound model.
// Accumulators stay float4 smem RMW (the 32-bit RMW variant measured 391us
// in R15 and is banned). Per-warp private copies -> no atomics in hot loop.
// ---------------------------------------------------------------------------
__global__ __launch_bounds__(BLOCK_THREADS)
void CLIR_accum_kernel(const float* __restrict__ x,
                       const int*   __restrict__ t,
                       int N) {
    __shared__ float s_sum[WARPS_PER_BLOCK][NCLS * DIM];   // 20 KB
    __shared__ float s_sq [WARPS_PER_BLOCK][NCLS * DIM];   // 20 KB
    __shared__ unsigned int s_cnt[NCLS];

    const int tid  = threadIdx.x;
    const int lane = tid & 31;
    const int w    = tid >> 5;

    float* s_sum_flat = &s_sum[0][0];
    float* s_sq_flat  = &s_sq[0][0];
    for (int i = tid; i < WARPS_PER_BLOCK * NCLS * DIM; i += BLOCK_THREADS) {
        s_sum_flat[i] = 0.0f;
        s_sq_flat[i]  = 0.0f;
    }
    if (tid < NCLS) s_cnt[tid] = 0u;
    __syncthreads();

    float* ms = s_sum[w];
    float* mq = s_sq[w];
    const float4* __restrict__ x4 = (const float4*)x;
    const int gw = blockIdx.x * WARPS_PER_BLOCK + w;

    #define ROWUPD(v, c) do {                                            \
        float4* ps = (float4*)(ms + (c) * DIM + lane * 4);               \
        float4* pq = (float4*)(mq + (c) * DIM + lane * 4);               \
        float4 a = *ps;                                                  \
        float4 b = *pq;                                                  \
        a.x += (v).x; a.y += (v).y; a.z += (v).z; a.w += (v).w;          \
        b.x = fmaf((v).x,(v).x,b.x); b.y = fmaf((v).y,(v).y,b.y);        \
        b.z = fmaf((v).z,(v).z,b.z); b.w = fmaf((v).w,(v).w,b.w);        \
        *ps = a;                                                         \
        *pq = b;                                                         \
        if (lane == 0) atomicAdd(&s_cnt[(c)], 1u);                       \
    } while (0)

    for (int base = gw * 2; base < N; base += GRID_BLOCKS * WARPS_PER_BLOCK * 2) {
        if (base + 2 <= N) {
            const int2 lab = __ldg((const int2*)(t + base));      // 8B aligned
            const float4 v0 = x4[(size_t)(base + 0) * (DIM / 4) + lane];
            const float4 v1 = x4[(size_t)(base + 1) * (DIM / 4) + lane];
            ROWUPD(v0, lab.x);
            ROWUPD(v1, lab.y);
        } else {
            const int c = __ldg(&t[base]);
            const float4 v = x4[(size_t)base * (DIM / 4) + lane];
            ROWUPD(v, c);
        }
    }
    #undef ROWUPD
    __syncthreads();

    // Fold the 4 warp-copies and push to global via spread float atomics
    // (exact R2 epilogue).
    for (int i = tid; i < NCLS * DIM; i += BLOCK_THREADS) {
        float vs = s_sum[0][i] + s_sum[1][i] + s_sum[2][i] + s_sum[3][i];
        float vq = s_sq[0][i]  + s_sq[1][i]  + s_sq[2][i]  + s_sq[3][i];
        atomicAdd(&g_sum[i], vs);
        atomicAdd(&g_sq[i],  vq);
    }
    if (tid < NCLS) atomicAdd(&g_cnt[tid], s_cnt[tid]);
}

// ---------------------------------------------------------------------------
// Exact R2 finalize: trace_c = Sum_d (SumSq[c][d] - Sum[c][d]^2/n) / (n-1);
// out = mean over classes.
// ---------------------------------------------------------------------------
__global__ void CLIR_finalize_kernel(float* __restrict__ out) {
    const int d = threadIdx.x;   // 128 threads
    float acc = 0.0f;
    #pragma unroll
    for (int c = 0; c < NCLS; c++) {
        const float n = (float)g_cnt[c];
        const float s = g_sum[c * DIM + d];
        const float q = g_sq [c * DIM + d];
        acc += (q - s * s / n) / (n - 1.0f);
    }
    #pragma unroll
    for (int o = 16; o > 0; o >>= 1)
        acc += __shfl_xor_sync(0xFFFFFFFFu, acc, o);
    __shared__ float wr[4];
    if ((d & 31) == 0) wr[d >> 5] = acc;
    __syncthreads();
    if (d == 0)
        out[0] = (wr[0] + wr[1] + wr[2] + wr[3]) * (1.0f / (float)NCLS);
}

extern "C" void kernel_launch(void* const* d_in, const int* in_sizes, int n_in,
                              void* d_out, int out_size) {
    const float* x = (const float*)d_in[0];
    const int*   t = (const int*)d_in[1];
    const int N = in_sizes[1];

    CLIR_zero_kernel<<<(NCLS * DIM + 255) / 256, 256>>>();
    CLIR_accum_kernel<<<GRID_BLOCKS, BLOCK_THREADS>>>(x, t, N);
    CLIR_finalize_kernel<<<1, DIM>>>((float*)d_out);
}